// round 2
// baseline (speedup 1.0000x reference)
#include <cuda_runtime.h>
#include <math.h>

#define CH   64
#define HH   256
#define WW   256
#define HWX  65536
#define NPIX (2*HWX)

// Precomputed-constant buffer layout (floats)
#define OFF_QWS  0        // [c][o] folded q weights        (4096)
#define OFF_KWS  4096     // [c][o] folded k weights        (4096)
#define OFF_VWS  8192     // [c][o] folded v weights        (4096)
#define OFF_QWPE 12288    // [j][t4][o] PE-rearranged q_w   (8192)
#define OFF_KB   20480    // [uv][o] k pe-bias              (256)
#define OFF_VB   20736    // [uv][o] v pe-bias              (256)
#define OFF_QB   20992    // q bias                          (64)
#define OFF_FREQ 21056    // 10000^(-j/32)                   (32)
#define NCONST   21088

__device__ float d_const[NCONST];

// ---------------------------------------------------------------------------
// Setup kernel: fold weights, precompute window-PE biases and frequencies.
// ---------------------------------------------------------------------------
__global__ void iw_setup_kernel(const float* __restrict__ qw, const float* __restrict__ qb,
                                const float* __restrict__ kw, const float* __restrict__ kb,
                                const float* __restrict__ vw, const float* __restrict__ vb)
{
    int t = threadIdx.x;

    // folded weights: ws[c][o] = w[o][2c] + w[o][2c+1]
    for (int i = t; i < 4096; i += blockDim.x) {
        int c = i >> 6, o = i & 63;
        d_const[OFF_QWS + i] = qw[o*128 + 2*c] + qw[o*128 + 2*c + 1];
        d_const[OFF_KWS + i] = kw[o*128 + 2*c] + kw[o*128 + 2*c + 1];
        d_const[OFF_VWS + i] = vw[o*128 + 2*c] + vw[o*128 + 2*c + 1];
    }

    // PE-rearranged q weights: [j][t4][o], t4: 0=sin_y,1=cos_y,2=sin_x,3=cos_x
    for (int i = t; i < 8192; i += blockDim.x) {
        int j = i >> 8, r = i & 255, t4 = r >> 6, o = r & 63;
        int col = (t4 < 2) ? (2*j + t4) : (64 + 2*j + (t4 - 2));
        d_const[OFF_QWPE + i] = qw[o*128 + col];
    }

    if (t < 32) d_const[OFF_FREQ + t] = powf(10000.0f, -(float)t / 32.0f);
    if (t < 64) d_const[OFF_QB + t]   = qb[t];

    // window-PE biases: kbias[uv][o] = pe_warp[uv] . k_w[o] + k_b[o]
    // pe_warp uses card = (U-1, V-1) = (1,1)
    const float SW = (float)(2.0 * M_PI / (1.0 + 1e-6));
    for (int i = t; i < 256; i += blockDim.x) {
        int uv = i >> 6, o = i & 63;
        float uu = (float)(uv >> 1), vv = (float)(uv & 1);
        float aK = kb[o], aV = vb[o];
        for (int j = 0; j < 32; j++) {
            float f  = powf(10000.0f, -(float)j / 32.0f);
            float ty = uu * SW * f;
            float tx = vv * SW * f;
            float syv = sinf(ty), cyv = cosf(ty);
            float sxv = sinf(tx), cxv = cosf(tx);
            aK += syv*kw[o*128+2*j] + cyv*kw[o*128+2*j+1]
                + sxv*kw[o*128+64+2*j] + cxv*kw[o*128+64+2*j+1];
            aV += syv*vw[o*128+2*j] + cyv*vw[o*128+2*j+1]
                + sxv*vw[o*128+64+2*j] + cxv*vw[o*128+64+2*j+1];
        }
        d_const[OFF_KB + i] = aK;
        d_const[OFF_VB + i] = aV;
    }
}

// ---------------------------------------------------------------------------
// Main kernel: one lane = one pixel. All weights broadcast from smem.
// ---------------------------------------------------------------------------
__global__ void __launch_bounds__(128) iw_main_kernel(
    const float* __restrict__ supp, const float* __restrict__ flow,
    const float* __restrict__ curr, float* __restrict__ out)
{
    extern __shared__ float sm[];
    for (int i = threadIdx.x; i < NCONST; i += 128) sm[i] = d_const[i];
    __syncthreads();

    const float* s_qws  = sm + OFF_QWS;
    const float* s_kws  = sm + OFF_KWS;
    const float* s_vws  = sm + OFF_VWS;
    const float* s_qwpe = sm + OFF_QWPE;
    const float* s_kb   = sm + OFF_KB;
    const float* s_vb   = sm + OFF_VB;
    const float* s_qb   = sm + OFF_QB;
    const float* s_fr   = sm + OFF_FREQ;

    int pix = blockIdx.x * 128 + threadIdx.x;
    int b   = pix >> 16;
    int rem = pix & 65535;
    int yy  = rem >> 8;
    int xx  = rem & 255;

    float2 fl = reinterpret_cast<const float2*>(flow)[pix];
    float gy = (float)yy + fl.y;            // flow[...,::-1]: y uses component 1
    float gx = (float)xx + fl.x;
    float fy = floorf(gy), fx = floorf(gx);
    float dy = gy - fy,    dx = gx - fx;    // fractional part (unclipped)
    int iy = (int)fy, ix = (int)fx;
    int r0 = min(max(iy,     0), HH-1);
    int r1 = min(max(iy + 1, 0), HH-1);
    int c0 = min(max(ix,     0), WW-1);
    int c1 = min(max(ix + 1, 0), WW-1);
    int o00 = r0*WW + c0, o01 = r0*WW + c1;
    int o10 = r1*WW + c0, o11 = r1*WW + c1;

    const float* suppB = supp + b*(CH*HWX);
    const float* currB = curr + b*(CH*HWX) + yy*WW + xx;

    // -------- q = (feat_curr folded) @ qws + PE matvec + qb --------
    float q[64];
    #pragma unroll
    for (int o = 0; o < 64; o++) q[o] = s_qb[o];

    #pragma unroll 4
    for (int c = 0; c < 64; c++) {
        float fc = __ldg(currB + c*HWX);
        const float* wc = s_qws + c*64;
        #pragma unroll
        for (int o = 0; o < 64; o++) q[o] = fmaf(fc, wc[o], q[o]);
    }

    const float PE2 = (float)(2.0 * M_PI / (2.0 + 1e-6));  // card = (U,V) = (2,2)
    float ay = dy * PE2, ax = dx * PE2;
    for (int j = 0; j < 32; j++) {
        float f = s_fr[j];
        float syv, cyv, sxv, cxv;
        __sincosf(ay * f, &syv, &cyv);
        __sincosf(ax * f, &sxv, &cxv);
        const float* wj = s_qwpe + j*256;
        #pragma unroll
        for (int o = 0; o < 64; o++) {
            float acc = q[o];
            acc = fmaf(syv, wj[o],       acc);
            acc = fmaf(cyv, wj[64  + o], acc);
            acc = fmaf(sxv, wj[128 + o], acc);
            acc = fmaf(cxv, wj[192 + o], acc);
            q[o] = acc;
        }
    }

    // -------- attention logits: bias-dot + folded qk pass over gather --------
    float attn[8][4];
    #pragma unroll
    for (int h = 0; h < 8; h++) {
        attn[h][0] = 0.f; attn[h][1] = 0.f; attn[h][2] = 0.f; attn[h][3] = 0.f;
    }

    #pragma unroll
    for (int o = 0; o < 64; o++) {
        int h = o >> 3;
        attn[h][0] = fmaf(q[o], s_kb[o],       attn[h][0]);
        attn[h][1] = fmaf(q[o], s_kb[64  + o], attn[h][1]);
        attn[h][2] = fmaf(q[o], s_kb[128 + o], attn[h][2]);
        attn[h][3] = fmaf(q[o], s_kb[192 + o], attn[h][3]);
    }

    for (int ch = 0; ch < 8; ch++) {
        float f00[8], f01[8], f10[8], f11[8];
        #pragma unroll
        for (int cc = 0; cc < 8; cc++) {
            const float* p = suppB + (ch*8 + cc)*HWX;
            f00[cc] = __ldg(p + o00);
            f01[cc] = __ldg(p + o01);
            f10[cc] = __ldg(p + o10);
            f11[cc] = __ldg(p + o11);
        }
        #pragma unroll
        for (int cc = 0; cc < 8; cc++) {
            const float* wc = s_kws + (ch*8 + cc)*64;
            #pragma unroll
            for (int h = 0; h < 8; h++) {
                float qk = q[h*8] * wc[h*8];
                #pragma unroll
                for (int e = 1; e < 8; e++) qk = fmaf(q[h*8 + e], wc[h*8 + e], qk);
                attn[h][0] = fmaf(qk, f00[cc], attn[h][0]);
                attn[h][1] = fmaf(qk, f01[cc], attn[h][1]);
                attn[h][2] = fmaf(qk, f10[cc], attn[h][2]);
                attn[h][3] = fmaf(qk, f11[cc], attn[h][3]);
            }
        }
    }

    // -------- softmax over the 4 window positions (scale = 8^-0.5) --------
    const float SC = 0.35355339059327376f;
    #pragma unroll
    for (int h = 0; h < 8; h++) {
        float m = fmaxf(fmaxf(attn[h][0], attn[h][1]), fmaxf(attn[h][2], attn[h][3]));
        float p0 = __expf((attn[h][0] - m) * SC);
        float p1 = __expf((attn[h][1] - m) * SC);
        float p2 = __expf((attn[h][2] - m) * SC);
        float p3 = __expf((attn[h][3] - m) * SC);
        float inv = __fdividef(1.0f, p0 + p1 + p2 + p3);
        attn[h][0] = p0*inv; attn[h][1] = p1*inv; attn[h][2] = p2*inv; attn[h][3] = p3*inv;
    }

    // -------- output: g-fold over second gather pass --------
    float outp[64];
    #pragma unroll
    for (int o = 0; o < 64; o++) outp[o] = 0.f;

    for (int ch = 0; ch < 8; ch++) {
        float f00[8], f01[8], f10[8], f11[8];
        #pragma unroll
        for (int cc = 0; cc < 8; cc++) {
            const float* p = suppB + (ch*8 + cc)*HWX;
            f00[cc] = __ldg(p + o00);
            f01[cc] = __ldg(p + o01);
            f10[cc] = __ldg(p + o10);
            f11[cc] = __ldg(p + o11);
        }
        #pragma unroll
        for (int cc = 0; cc < 8; cc++) {
            const float* wc = s_vws + (ch*8 + cc)*64;
            float gv[8];
            #pragma unroll
            for (int h = 0; h < 8; h++) {
                float g = attn[h][0] * f00[cc];
                g = fmaf(attn[h][1], f01[cc], g);
                g = fmaf(attn[h][2], f10[cc], g);
                g = fmaf(attn[h][3], f11[cc], g);
                gv[h] = g;
            }
            #pragma unroll
            for (int o = 0; o < 64; o++) outp[o] = fmaf(gv[o >> 3], wc[o], outp[o]);
        }
    }

    // v pe-bias term
    #pragma unroll
    for (int o = 0; o < 64; o++) {
        int h = o >> 3;
        float acc = outp[o];
        acc = fmaf(attn[h][0], s_vb[o],       acc);
        acc = fmaf(attn[h][1], s_vb[64  + o], acc);
        acc = fmaf(attn[h][2], s_vb[128 + o], acc);
        acc = fmaf(attn[h][3], s_vb[192 + o], acc);
        outp[o] = acc;
    }

    float* outB = out + b*(CH*HWX) + yy*WW + xx;
    #pragma unroll
    for (int o = 0; o < 64; o++) outB[o*HWX] = outp[o];
}

// ---------------------------------------------------------------------------
extern "C" void kernel_launch(void* const* d_in, const int* in_sizes, int n_in,
                              void* d_out, int out_size)
{
    const float* supp = (const float*)d_in[0];
    const float* flow = (const float*)d_in[1];
    const float* curr = (const float*)d_in[2];
    const float* qw   = (const float*)d_in[3];
    const float* qb   = (const float*)d_in[4];
    const float* kw   = (const float*)d_in[5];
    const float* kb   = (const float*)d_in[6];
    const float* vw   = (const float*)d_in[7];
    const float* vb   = (const float*)d_in[8];
    float* outp = (float*)d_out;

    cudaFuncSetAttribute(iw_main_kernel,
                         cudaFuncAttributeMaxDynamicSharedMemorySize, NCONST * 4);

    iw_setup_kernel<<<1, 256>>>(qw, qb, kw, kb, vw, vb);
    iw_main_kernel<<<NPIX / 128, 128, NCONST * 4>>>(supp, flow, curr, outp);
}

// round 3
// speedup vs baseline: 1.5963x; 1.5963x over previous
#include <cuda_runtime.h>
#include <math.h>

#define CH   64
#define HH   256
#define WW   256
#define HWX  65536
#define NPIX (2*HWX)

// Precomputed-constant buffer layout (floats) in d_const
#define OFF_QWS  0        // [c][o] folded q weights        (4096)
#define OFF_KWS  4096     // [c][o] folded k weights        (4096)
#define OFF_VWS  8192     // [c][o] folded v weights        (4096)
#define OFF_QWPE 12288    // [j][t4][o] PE-rearranged q_w   (8192)
#define OFF_KB   20480    // [uv][o] k pe-bias              (256)
#define OFF_VB   20736    // [uv][o] v pe-bias              (256)
#define OFF_QB   20992    // q bias                          (64)
#define OFF_FREQ 21056    // 10000^(-j/32)                   (32)
#define NCONST   21088

__device__ float d_const[NCONST];
__device__ float q_scr[64 * NPIX];   // q scratch, [o][pix]

// Q-kernel smem layout (floats)
#define QS_QWS  0
#define QS_QWPE 4096
#define QS_QB   12288
#define QS_FREQ 12352
#define QS_N    12384     // 49536 B

// AV-kernel smem layout (floats)
#define AS_KWS  0
#define AS_VWS  4096
#define AS_KB   8192
#define AS_VB   8448
#define AS_N    8704      // 34816 B

// ---------------------------------------------------------------------------
// Setup kernel: fold weights, precompute window-PE biases and frequencies.
// ---------------------------------------------------------------------------
__global__ void iw_setup_kernel(const float* __restrict__ qw, const float* __restrict__ qb,
                                const float* __restrict__ kw, const float* __restrict__ kb,
                                const float* __restrict__ vw, const float* __restrict__ vb)
{
    int t = threadIdx.x;

    // folded weights: ws[c][o] = w[o][2c] + w[o][2c+1]
    for (int i = t; i < 4096; i += blockDim.x) {
        int c = i >> 6, o = i & 63;
        d_const[OFF_QWS + i] = qw[o*128 + 2*c] + qw[o*128 + 2*c + 1];
        d_const[OFF_KWS + i] = kw[o*128 + 2*c] + kw[o*128 + 2*c + 1];
        d_const[OFF_VWS + i] = vw[o*128 + 2*c] + vw[o*128 + 2*c + 1];
    }

    // PE-rearranged q weights: [j][t4][o], t4: 0=sin_y,1=cos_y,2=sin_x,3=cos_x
    for (int i = t; i < 8192; i += blockDim.x) {
        int j = i >> 8, r = i & 255, t4 = r >> 6, o = r & 63;
        int col = (t4 < 2) ? (2*j + t4) : (64 + 2*j + (t4 - 2));
        d_const[OFF_QWPE + i] = qw[o*128 + col];
    }

    if (t < 32) d_const[OFF_FREQ + t] = powf(10000.0f, -(float)t / 32.0f);
    if (t < 64) d_const[OFF_QB + t]   = qb[t];

    // window-PE biases: kbias[uv][o] = pe_warp[uv] . k_w[o] + k_b[o]
    // pe_warp uses card = (U-1, V-1) = (1,1)
    const float SW = (float)(2.0 * M_PI / (1.0 + 1e-6));
    for (int i = t; i < 256; i += blockDim.x) {
        int uv = i >> 6, o = i & 63;
        float uu = (float)(uv >> 1), vv = (float)(uv & 1);
        float aK = kb[o], aV = vb[o];
        for (int j = 0; j < 32; j++) {
            float f  = powf(10000.0f, -(float)j / 32.0f);
            float ty = uu * SW * f;
            float tx = vv * SW * f;
            float syv = sinf(ty), cyv = cosf(ty);
            float sxv = sinf(tx), cxv = cosf(tx);
            aK += syv*kw[o*128+2*j] + cyv*kw[o*128+2*j+1]
                + sxv*kw[o*128+64+2*j] + cxv*kw[o*128+64+2*j+1];
            aV += syv*vw[o*128+2*j] + cyv*vw[o*128+2*j+1]
                + sxv*vw[o*128+64+2*j] + cxv*vw[o*128+64+2*j+1];
        }
        d_const[OFF_KB + i] = aK;
        d_const[OFF_VB + i] = aV;
    }
}

// ---------------------------------------------------------------------------
// Q kernel: q = folded-curr matvec + PE matvec + bias. One lane = one pixel.
// ---------------------------------------------------------------------------
__global__ void __launch_bounds__(256, 2) iw_q_kernel(
    const float* __restrict__ curr, const float* __restrict__ flow)
{
    extern __shared__ float sm[];
    for (int i = threadIdx.x; i < 4096; i += 256) sm[QS_QWS  + i] = d_const[OFF_QWS  + i];
    for (int i = threadIdx.x; i < 8192; i += 256) sm[QS_QWPE + i] = d_const[OFF_QWPE + i];
    if (threadIdx.x < 64) sm[QS_QB   + threadIdx.x] = d_const[OFF_QB   + threadIdx.x];
    if (threadIdx.x < 32) sm[QS_FREQ + threadIdx.x] = d_const[OFF_FREQ + threadIdx.x];
    __syncthreads();

    const float* s_qws  = sm + QS_QWS;
    const float* s_qwpe = sm + QS_QWPE;
    const float* s_qb   = sm + QS_QB;
    const float* s_fr   = sm + QS_FREQ;

    int pix = blockIdx.x * 256 + threadIdx.x;
    int b   = pix >> 16;
    int rem = pix & 65535;
    int yy  = rem >> 8;
    int xx  = rem & 255;

    float2 fl = reinterpret_cast<const float2*>(flow)[pix];
    float gy = (float)yy + fl.y;
    float gx = (float)xx + fl.x;
    float dy = gy - floorf(gy);
    float dx = gx - floorf(gx);

    const float* currB = curr + b*(CH*HWX) + yy*WW + xx;

    float q[64];
    #pragma unroll
    for (int o = 0; o < 64; o++) q[o] = s_qb[o];

    #pragma unroll 4
    for (int c = 0; c < 64; c++) {
        float fc = __ldg(currB + c*HWX);
        const float* wc = s_qws + c*64;
        #pragma unroll
        for (int o = 0; o < 64; o++) q[o] = fmaf(fc, wc[o], q[o]);
    }

    const float PE2 = (float)(2.0 * M_PI / (2.0 + 1e-6));  // card = (U,V) = (2,2)
    float ay = dy * PE2, ax = dx * PE2;
    for (int j = 0; j < 32; j++) {
        float f = s_fr[j];
        float syv, cyv, sxv, cxv;
        __sincosf(ay * f, &syv, &cyv);
        __sincosf(ax * f, &sxv, &cxv);
        const float* wj = s_qwpe + j*256;
        #pragma unroll
        for (int o = 0; o < 64; o++) {
            float acc = q[o];
            acc = fmaf(syv, wj[o],       acc);
            acc = fmaf(cyv, wj[64  + o], acc);
            acc = fmaf(sxv, wj[128 + o], acc);
            acc = fmaf(cxv, wj[192 + o], acc);
            q[o] = acc;
        }
    }

    #pragma unroll
    for (int o = 0; o < 64; o++) q_scr[o*NPIX + pix] = q[o];
}

// ---------------------------------------------------------------------------
// AV kernel: gather + attn logits + softmax + value pass. One lane = one pixel.
// ---------------------------------------------------------------------------
__global__ void __launch_bounds__(128, 3) iw_av_kernel(
    const float* __restrict__ supp, const float* __restrict__ flow,
    float* __restrict__ out)
{
    extern __shared__ float sm[];
    for (int i = threadIdx.x; i < 4096; i += 128) {
        sm[AS_KWS + i] = d_const[OFF_KWS + i];
        sm[AS_VWS + i] = d_const[OFF_VWS + i];
    }
    for (int i = threadIdx.x; i < 256; i += 128) {
        sm[AS_KB + i] = d_const[OFF_KB + i];
        sm[AS_VB + i] = d_const[OFF_VB + i];
    }
    __syncthreads();

    const float* s_kws = sm + AS_KWS;
    const float* s_vws = sm + AS_VWS;
    const float* s_kb  = sm + AS_KB;
    const float* s_vb  = sm + AS_VB;

    int pix = blockIdx.x * 128 + threadIdx.x;
    int b   = pix >> 16;
    int rem = pix & 65535;
    int yy  = rem >> 8;
    int xx  = rem & 255;

    float2 fl = reinterpret_cast<const float2*>(flow)[pix];
    float gy = (float)yy + fl.y;
    float gx = (float)xx + fl.x;
    int iy = (int)floorf(gy), ix = (int)floorf(gx);
    int r0 = min(max(iy,     0), HH-1);
    int r1 = min(max(iy + 1, 0), HH-1);
    int c0 = min(max(ix,     0), WW-1);
    int c1 = min(max(ix + 1, 0), WW-1);
    int o00 = r0*WW + c0, o01 = r0*WW + c1;
    int o10 = r1*WW + c0, o11 = r1*WW + c1;

    const float* suppB = supp + b*(CH*HWX);

    // load q (coalesced per-o)
    float q[64];
    #pragma unroll
    for (int o = 0; o < 64; o++) q[o] = q_scr[o*NPIX + pix];

    // -------- attention logits: bias-dot + folded qk pass over gather --------
    float attn[8][4];
    #pragma unroll
    for (int h = 0; h < 8; h++) {
        attn[h][0] = 0.f; attn[h][1] = 0.f; attn[h][2] = 0.f; attn[h][3] = 0.f;
    }

    #pragma unroll
    for (int o = 0; o < 64; o++) {
        int h = o >> 3;
        attn[h][0] = fmaf(q[o], s_kb[o],       attn[h][0]);
        attn[h][1] = fmaf(q[o], s_kb[64  + o], attn[h][1]);
        attn[h][2] = fmaf(q[o], s_kb[128 + o], attn[h][2]);
        attn[h][3] = fmaf(q[o], s_kb[192 + o], attn[h][3]);
    }

    for (int ch = 0; ch < 8; ch++) {
        float f00[8], f01[8], f10[8], f11[8];
        #pragma unroll
        for (int cc = 0; cc < 8; cc++) {
            const float* p = suppB + (ch*8 + cc)*HWX;
            f00[cc] = __ldg(p + o00);
            f01[cc] = __ldg(p + o01);
            f10[cc] = __ldg(p + o10);
            f11[cc] = __ldg(p + o11);
        }
        #pragma unroll
        for (int cc = 0; cc < 8; cc++) {
            const float* wc = s_kws + (ch*8 + cc)*64;
            #pragma unroll
            for (int h = 0; h < 8; h++) {
                float qk = q[h*8] * wc[h*8];
                #pragma unroll
                for (int e = 1; e < 8; e++) qk = fmaf(q[h*8 + e], wc[h*8 + e], qk);
                attn[h][0] = fmaf(qk, f00[cc], attn[h][0]);
                attn[h][1] = fmaf(qk, f01[cc], attn[h][1]);
                attn[h][2] = fmaf(qk, f10[cc], attn[h][2]);
                attn[h][3] = fmaf(qk, f11[cc], attn[h][3]);
            }
        }
    }

    // -------- softmax over the 4 window positions (scale = 8^-0.5) --------
    const float SC = 0.35355339059327376f;
    #pragma unroll
    for (int h = 0; h < 8; h++) {
        float m = fmaxf(fmaxf(attn[h][0], attn[h][1]), fmaxf(attn[h][2], attn[h][3]));
        float p0 = __expf((attn[h][0] - m) * SC);
        float p1 = __expf((attn[h][1] - m) * SC);
        float p2 = __expf((attn[h][2] - m) * SC);
        float p3 = __expf((attn[h][3] - m) * SC);
        float inv = __fdividef(1.0f, p0 + p1 + p2 + p3);
        attn[h][0] = p0*inv; attn[h][1] = p1*inv; attn[h][2] = p2*inv; attn[h][3] = p3*inv;
    }

    // -------- output: g-fold over second gather pass (L1-hit reloads) --------
    float outp[64];
    #pragma unroll
    for (int o = 0; o < 64; o++) outp[o] = 0.f;

    for (int ch = 0; ch < 8; ch++) {
        float f00[8], f01[8], f10[8], f11[8];
        #pragma unroll
        for (int cc = 0; cc < 8; cc++) {
            const float* p = suppB + (ch*8 + cc)*HWX;
            f00[cc] = __ldg(p + o00);
            f01[cc] = __ldg(p + o01);
            f10[cc] = __ldg(p + o10);
            f11[cc] = __ldg(p + o11);
        }
        #pragma unroll
        for (int cc = 0; cc < 8; cc++) {
            const float* wc = s_vws + (ch*8 + cc)*64;
            float gv[8];
            #pragma unroll
            for (int h = 0; h < 8; h++) {
                float g = attn[h][0] * f00[cc];
                g = fmaf(attn[h][1], f01[cc], g);
                g = fmaf(attn[h][2], f10[cc], g);
                g = fmaf(attn[h][3], f11[cc], g);
                gv[h] = g;
            }
            #pragma unroll
            for (int o = 0; o < 64; o++) outp[o] = fmaf(gv[o >> 3], wc[o], outp[o]);
        }
    }

    // v pe-bias term
    #pragma unroll
    for (int o = 0; o < 64; o++) {
        int h = o >> 3;
        float acc = outp[o];
        acc = fmaf(attn[h][0], s_vb[o],       acc);
        acc = fmaf(attn[h][1], s_vb[64  + o], acc);
        acc = fmaf(attn[h][2], s_vb[128 + o], acc);
        acc = fmaf(attn[h][3], s_vb[192 + o], acc);
        outp[o] = acc;
    }

    float* outB = out + b*(CH*HWX) + yy*WW + xx;
    #pragma unroll
    for (int o = 0; o < 64; o++) outB[o*HWX] = outp[o];
}

// ---------------------------------------------------------------------------
extern "C" void kernel_launch(void* const* d_in, const int* in_sizes, int n_in,
                              void* d_out, int out_size)
{
    const float* supp = (const float*)d_in[0];
    const float* flow = (const float*)d_in[1];
    const float* curr = (const float*)d_in[2];
    const float* qw   = (const float*)d_in[3];
    const float* qb   = (const float*)d_in[4];
    const float* kw   = (const float*)d_in[5];
    const float* kb   = (const float*)d_in[6];
    const float* vw   = (const float*)d_in[7];
    const float* vb   = (const float*)d_in[8];
    float* outp = (float*)d_out;

    cudaFuncSetAttribute(iw_q_kernel,
                         cudaFuncAttributeMaxDynamicSharedMemorySize, QS_N * 4);
    cudaFuncSetAttribute(iw_av_kernel,
                         cudaFuncAttributeMaxDynamicSharedMemorySize, AS_N * 4);

    iw_setup_kernel<<<1, 256>>>(qw, qb, kw, kb, vw, vb);
    iw_q_kernel<<<NPIX / 256, 256, QS_N * 4>>>(curr, flow);
    iw_av_kernel<<<NPIX / 128, 128, AS_N * 4>>>(supp, flow, outp);
}

// round 5
// speedup vs baseline: 1.6634x; 1.0420x over previous
#include <cuda_runtime.h>
#include <math.h>

#define CH   64
#define HH   256
#define WW   256
#define HWX  65536
#define NPIX (2*HWX)

// Precomputed-constant buffer layout (floats) in d_const
#define OFF_QWS  0        // [c][o] folded q weights        (4096)
#define OFF_KWS  4096     // [c][o] folded k weights        (4096)
#define OFF_VWS  8192     // [c][o] folded v weights        (4096)
#define OFF_QWPE 12288    // [j][t4][o] PE-rearranged q_w   (8192)
#define OFF_KB   20480    // [uv][o] k pe-bias              (256)
#define OFF_VB   20736    // [uv][o] v pe-bias              (256)
#define OFF_QB   20992    // q bias                          (64)
#define OFF_FREQ 21056    // 10000^(-j/32)                   (32)
#define NCONST   21088

__device__ float d_const[NCONST];
__device__ float q_scr[64 * NPIX];   // q scratch, [o][pix]

// Q-kernel smem layout (floats)
#define QS_QWS  0
#define QS_QWPE 4096
#define QS_QB   12288
#define QS_FREQ 12352
#define QS_N    12384     // 49536 B

// AV-kernel smem layout (floats)
#define AS_KWS  0
#define AS_VWS  4096
#define AS_KB   8192
#define AS_VB   8448
#define AS_N    8704      // 34816 B

// ---------------------------------------------------------------------------
// Setup kernel: fold weights, precompute window-PE biases and frequencies.
// Grid-strided across 64 blocks so no single SM serializes the work.
// ---------------------------------------------------------------------------
__global__ void iw_setup_kernel(const float* __restrict__ qw, const float* __restrict__ qb,
                                const float* __restrict__ kw, const float* __restrict__ kb,
                                const float* __restrict__ vw, const float* __restrict__ vb)
{
    const int g      = blockIdx.x * blockDim.x + threadIdx.x;
    const int stride = gridDim.x * blockDim.x;
    const float LN1E4_32 = 9.210340371976184f / 32.0f;   // ln(10000)/32

    // folded weights: ws[c][o] = w[o][2c] + w[o][2c+1]
    for (int i = g; i < 4096; i += stride) {
        int c = i >> 6, o = i & 63;
        d_const[OFF_QWS + i] = qw[o*128 + 2*c] + qw[o*128 + 2*c + 1];
        d_const[OFF_KWS + i] = kw[o*128 + 2*c] + kw[o*128 + 2*c + 1];
        d_const[OFF_VWS + i] = vw[o*128 + 2*c] + vw[o*128 + 2*c + 1];
    }

    // PE-rearranged q weights: [j][t4][o], t4: 0=sin_y,1=cos_y,2=sin_x,3=cos_x
    for (int i = g; i < 8192; i += stride) {
        int j = i >> 8, r = i & 255, t4 = r >> 6, o = r & 63;
        int col = (t4 < 2) ? (2*j + t4) : (64 + 2*j + (t4 - 2));
        d_const[OFF_QWPE + i] = qw[o*128 + col];
    }

    if (g < 32) d_const[OFF_FREQ + g] = __expf(-(float)g * LN1E4_32);
    if (g < 64) d_const[OFF_QB + g]   = qb[g];

    // window-PE biases: kbias[uv][o] = pe_warp[uv] . k_w[o] + k_b[o]
    // pe_warp uses card = (U-1, V-1) = (1,1). One thread per (uv,o) entry.
    const float SW = (float)(2.0 * M_PI / (1.0 + 1e-6));
    for (int i = g; i < 256; i += stride) {
        int uv = i >> 6, o = i & 63;
        float uu = (float)(uv >> 1), vv = (float)(uv & 1);
        float aK = kb[o], aV = vb[o];
        #pragma unroll 4
        for (int j = 0; j < 32; j++) {
            float f  = __expf(-(float)j * LN1E4_32);
            float ty = uu * SW * f;
            float tx = vv * SW * f;
            float syv, cyv, sxv, cxv;
            __sincosf(ty, &syv, &cyv);
            __sincosf(tx, &sxv, &cxv);
            aK += syv*kw[o*128+2*j] + cyv*kw[o*128+2*j+1]
                + sxv*kw[o*128+64+2*j] + cxv*kw[o*128+64+2*j+1];
            aV += syv*vw[o*128+2*j] + cyv*vw[o*128+2*j+1]
                + sxv*vw[o*128+64+2*j] + cxv*vw[o*128+64+2*j+1];
        }
        d_const[OFF_KB + i] = aK;
        d_const[OFF_VB + i] = aV;
    }
}

// ---------------------------------------------------------------------------
// Q kernel: q = folded-curr matvec + PE matvec + bias. One lane = one pixel.
// ---------------------------------------------------------------------------
__global__ void __launch_bounds__(256, 2) iw_q_kernel(
    const float* __restrict__ curr, const float* __restrict__ flow)
{
    extern __shared__ float sm[];
    for (int i = threadIdx.x; i < 4096; i += 256) sm[QS_QWS  + i] = d_const[OFF_QWS  + i];
    for (int i = threadIdx.x; i < 8192; i += 256) sm[QS_QWPE + i] = d_const[OFF_QWPE + i];
    if (threadIdx.x < 64) sm[QS_QB   + threadIdx.x] = d_const[OFF_QB   + threadIdx.x];
    if (threadIdx.x < 32) sm[QS_FREQ + threadIdx.x] = d_const[OFF_FREQ + threadIdx.x];
    __syncthreads();

    const float* s_qws  = sm + QS_QWS;
    const float* s_qwpe = sm + QS_QWPE;
    const float* s_qb   = sm + QS_QB;
    const float* s_fr   = sm + QS_FREQ;

    int pix = blockIdx.x * 256 + threadIdx.x;
    int b   = pix >> 16;
    int rem = pix & 65535;
    int yy  = rem >> 8;
    int xx  = rem & 255;

    float2 fl = reinterpret_cast<const float2*>(flow)[pix];
    float gy = (float)yy + fl.y;
    float gx = (float)xx + fl.x;
    float dy = gy - floorf(gy);
    float dx = gx - floorf(gx);

    const float* currB = curr + b*(CH*HWX) + yy*WW + xx;

    float q[64];
    #pragma unroll
    for (int o = 0; o < 64; o++) q[o] = s_qb[o];

    #pragma unroll 4
    for (int c = 0; c < 64; c++) {
        float fc = __ldg(currB + c*HWX);
        const float* wc = s_qws + c*64;
        #pragma unroll
        for (int o = 0; o < 64; o++) q[o] = fmaf(fc, wc[o], q[o]);
    }

    const float PE2 = (float)(2.0 * M_PI / (2.0 + 1e-6));  // card = (U,V) = (2,2)
    float ay = dy * PE2, ax = dx * PE2;
    for (int j = 0; j < 32; j++) {
        float f = s_fr[j];
        float syv, cyv, sxv, cxv;
        __sincosf(ay * f, &syv, &cyv);
        __sincosf(ax * f, &sxv, &cxv);
        const float* wj = s_qwpe + j*256;
        #pragma unroll
        for (int o = 0; o < 64; o++) {
            float acc = q[o];
            acc = fmaf(syv, wj[o],       acc);
            acc = fmaf(cyv, wj[64  + o], acc);
            acc = fmaf(sxv, wj[128 + o], acc);
            acc = fmaf(cxv, wj[192 + o], acc);
            q[o] = acc;
        }
    }

    #pragma unroll
    for (int o = 0; o < 64; o++) q_scr[o*NPIX + pix] = q[o];
}

// ---------------------------------------------------------------------------
// AV kernel: gather + attn logits + softmax + value pass. One lane = one pixel.
// ---------------------------------------------------------------------------
__global__ void __launch_bounds__(128, 3) iw_av_kernel(
    const float* __restrict__ supp, const float* __restrict__ flow,
    float* __restrict__ out)
{
    extern __shared__ float sm[];
    for (int i = threadIdx.x; i < 4096; i += 128) {
        sm[AS_KWS + i] = d_const[OFF_KWS + i];
        sm[AS_VWS + i] = d_const[OFF_VWS + i];
    }
    for (int i = threadIdx.x; i < 256; i += 128) {
        sm[AS_KB + i] = d_const[OFF_KB + i];
        sm[AS_VB + i] = d_const[OFF_VB + i];
    }
    __syncthreads();

    const float* s_kws = sm + AS_KWS;
    const float* s_vws = sm + AS_VWS;
    const float* s_kb  = sm + AS_KB;
    const float* s_vb  = sm + AS_VB;

    int pix = blockIdx.x * 128 + threadIdx.x;
    int b   = pix >> 16;
    int rem = pix & 65535;
    int yy  = rem >> 8;
    int xx  = rem & 255;

    float2 fl = reinterpret_cast<const float2*>(flow)[pix];
    float gy = (float)yy + fl.y;
    float gx = (float)xx + fl.x;
    int iy = (int)floorf(gy), ix = (int)floorf(gx);
    int r0 = min(max(iy,     0), HH-1);
    int r1 = min(max(iy + 1, 0), HH-1);
    int c0 = min(max(ix,     0), WW-1);
    int c1 = min(max(ix + 1, 0), WW-1);
    int o00 = r0*WW + c0, o01 = r0*WW + c1;
    int o10 = r1*WW + c0, o11 = r1*WW + c1;

    const float* suppB = supp + b*(CH*HWX);

    // load q (coalesced per-o)
    float q[64];
    #pragma unroll
    for (int o = 0; o < 64; o++) q[o] = q_scr[o*NPIX + pix];

    // -------- attention logits: bias-dot + folded qk pass over gather --------
    float attn[8][4];
    #pragma unroll
    for (int h = 0; h < 8; h++) {
        attn[h][0] = 0.f; attn[h][1] = 0.f; attn[h][2] = 0.f; attn[h][3] = 0.f;
    }

    #pragma unroll
    for (int o = 0; o < 64; o++) {
        int h = o >> 3;
        attn[h][0] = fmaf(q[o], s_kb[o],       attn[h][0]);
        attn[h][1] = fmaf(q[o], s_kb[64  + o], attn[h][1]);
        attn[h][2] = fmaf(q[o], s_kb[128 + o], attn[h][2]);
        attn[h][3] = fmaf(q[o], s_kb[192 + o], attn[h][3]);
    }

    for (int ch = 0; ch < 8; ch++) {
        float f00[8], f01[8], f10[8], f11[8];
        #pragma unroll
        for (int cc = 0; cc < 8; cc++) {
            const float* p = suppB + (ch*8 + cc)*HWX;
            f00[cc] = __ldg(p + o00);
            f01[cc] = __ldg(p + o01);
            f10[cc] = __ldg(p + o10);
            f11[cc] = __ldg(p + o11);
        }
        #pragma unroll
        for (int cc = 0; cc < 8; cc++) {
            const float* wc = s_kws + (ch*8 + cc)*64;
            #pragma unroll
            for (int h = 0; h < 8; h++) {
                float qk = q[h*8] * wc[h*8];
                #pragma unroll
                for (int e = 1; e < 8; e++) qk = fmaf(q[h*8 + e], wc[h*8 + e], qk);
                attn[h][0] = fmaf(qk, f00[cc], attn[h][0]);
                attn[h][1] = fmaf(qk, f01[cc], attn[h][1]);
                attn[h][2] = fmaf(qk, f10[cc], attn[h][2]);
                attn[h][3] = fmaf(qk, f11[cc], attn[h][3]);
            }
        }
    }

    // -------- softmax over the 4 window positions (scale = 8^-0.5) --------
    const float SC = 0.35355339059327376f;
    #pragma unroll
    for (int h = 0; h < 8; h++) {
        float m = fmaxf(fmaxf(attn[h][0], attn[h][1]), fmaxf(attn[h][2], attn[h][3]));
        float p0 = __expf((attn[h][0] - m) * SC);
        float p1 = __expf((attn[h][1] - m) * SC);
        float p2 = __expf((attn[h][2] - m) * SC);
        float p3 = __expf((attn[h][3] - m) * SC);
        float inv = __fdividef(1.0f, p0 + p1 + p2 + p3);
        attn[h][0] = p0*inv; attn[h][1] = p1*inv; attn[h][2] = p2*inv; attn[h][3] = p3*inv;
    }

    // -------- output: g-fold over second gather pass (L1-hit reloads) --------
    float outp[64];
    #pragma unroll
    for (int o = 0; o < 64; o++) outp[o] = 0.f;

    for (int ch = 0; ch < 8; ch++) {
        float f00[8], f01[8], f10[8], f11[8];
        #pragma unroll
        for (int cc = 0; cc < 8; cc++) {
            const float* p = suppB + (ch*8 + cc)*HWX;
            f00[cc] = __ldg(p + o00);
            f01[cc] = __ldg(p + o01);
            f10[cc] = __ldg(p + o10);
            f11[cc] = __ldg(p + o11);
        }
        #pragma unroll
        for (int cc = 0; cc < 8; cc++) {
            const float* wc = s_vws + (ch*8 + cc)*64;
            float gv[8];
            #pragma unroll
            for (int h = 0; h < 8; h++) {
                float g = attn[h][0] * f00[cc];
                g = fmaf(attn[h][1], f01[cc], g);
                g = fmaf(attn[h][2], f10[cc], g);
                g = fmaf(attn[h][3], f11[cc], g);
                gv[h] = g;
            }
            #pragma unroll
            for (int o = 0; o < 64; o++) outp[o] = fmaf(gv[o >> 3], wc[o], outp[o]);
        }
    }

    // v pe-bias term
    #pragma unroll
    for (int o = 0; o < 64; o++) {
        int h = o >> 3;
        float acc = outp[o];
        acc = fmaf(attn[h][0], s_vb[o],       acc);
        acc = fmaf(attn[h][1], s_vb[64  + o], acc);
        acc = fmaf(attn[h][2], s_vb[128 + o], acc);
        acc = fmaf(attn[h][3], s_vb[192 + o], acc);
        outp[o] = acc;
    }

    float* outB = out + b*(CH*HWX) + yy*WW + xx;
    #pragma unroll
    for (int o = 0; o < 64; o++) outB[o*HWX] = outp[o];
}

// ---------------------------------------------------------------------------
extern "C" void kernel_launch(void* const* d_in, const int* in_sizes, int n_in,
                              void* d_out, int out_size)
{
    const float* supp = (const float*)d_in[0];
    const float* flow = (const float*)d_in[1];
    const float* curr = (const float*)d_in[2];
    const float* qw   = (const float*)d_in[3];
    const float* qb   = (const float*)d_in[4];
    const float* kw   = (const float*)d_in[5];
    const float* kb   = (const float*)d_in[6];
    const float* vw   = (const float*)d_in[7];
    const float* vb   = (const float*)d_in[8];
    float* outp = (float*)d_out;

    cudaFuncSetAttribute(iw_q_kernel,
                         cudaFuncAttributeMaxDynamicSharedMemorySize, QS_N * 4);
    cudaFuncSetAttribute(iw_av_kernel,
                         cudaFuncAttributeMaxDynamicSharedMemorySize, AS_N * 4);

    iw_setup_kernel<<<64, 256>>>(qw, qb, kw, kb, vw, vb);
    iw_q_kernel<<<NPIX / 256, 256, QS_N * 4>>>(curr, flow);
    iw_av_kernel<<<NPIX / 128, 128, AS_N * 4>>>(supp, flow, outp);
}

// round 7
// speedup vs baseline: 2.0296x; 1.2202x over previous
#include <cuda_runtime.h>
#include <math.h>

#define CH   64
#define HH   256
#define WW   256
#define HWX  65536
#define NPIX (2*HWX)

typedef unsigned long long u64t;

__device__ __forceinline__ u64t pk2(float lo, float hi) {
    u64t r; asm("mov.b64 %0,{%1,%2};" : "=l"(r) : "f"(lo), "f"(hi)); return r;
}
__device__ __forceinline__ void upk2(float& lo, float& hi, u64t v) {
    asm("mov.b64 {%0,%1},%2;" : "=f"(lo), "=f"(hi) : "l"(v));
}
__device__ __forceinline__ u64t ffma2(u64t a, u64t b, u64t c) {
    u64t d; asm("fma.rn.f32x2 %0,%1,%2,%3;" : "=l"(d) : "l"(a), "l"(b), "l"(c)); return d;
}
__device__ __forceinline__ u64t fmul2(u64t a, u64t b) {
    u64t d; asm("mul.rn.f32x2 %0,%1,%2;" : "=l"(d) : "l"(a), "l"(b)); return d;
}

// Precomputed-constant buffer layout (floats) in d_const
#define OFF_QWS  0        // [c][o] folded q weights        (4096)
#define OFF_KWS  4096     // [c][o] folded k weights        (4096)
#define OFF_VWS  8192     // [c][o] folded v weights        (4096)
#define OFF_QWPE 12288    // [j][t4][o] PE-rearranged q_w   (8192)
#define OFF_KB   20480    // [uv][o] k pe-bias              (256)
#define OFF_VB   20736    // [uv][o] v pe-bias              (256)
#define OFF_QB   20992    // q bias                          (64)
#define OFF_FREQ 21056    // 10000^(-j/32)                   (32)
#define NCONST   21088

__device__ float d_const[NCONST];
__device__ float q_scr[64 * NPIX];   // q scratch, [o][pix]

// Q-kernel smem layout (floats)
#define QS_QWS  0
#define QS_QWPE 4096
#define QS_QB   12288
#define QS_FREQ 12352
#define QS_N    12384     // 49536 B

// AV-kernel smem layout (floats)
#define AS_KWS  0
#define AS_VWS  4096
#define AS_KB   8192
#define AS_VB   8448
#define AS_N    8704      // 34816 B

// ---------------------------------------------------------------------------
// Setup kernel: 32 blocks x 256. Bias computation: one warp per (uv,o),
// lane = frequency index j, butterfly reduction. One memory round-trip deep.
// ---------------------------------------------------------------------------
__global__ void iw_setup_kernel(const float* __restrict__ qw, const float* __restrict__ qb,
                                const float* __restrict__ kw, const float* __restrict__ kb,
                                const float* __restrict__ vw, const float* __restrict__ vb)
{
    const int g = blockIdx.x * 256 + threadIdx.x;      // 8192 threads total
    const float LN1E4_32 = 9.210340371976184f / 32.0f; // ln(10000)/32

    // folded weights: ws[c][o] = w[o][2c] + w[o][2c+1]
    if (g < 4096) {
        int c = g >> 6, o = g & 63;
        d_const[OFF_QWS + g] = qw[o*128 + 2*c] + qw[o*128 + 2*c + 1];
        d_const[OFF_KWS + g] = kw[o*128 + 2*c] + kw[o*128 + 2*c + 1];
        d_const[OFF_VWS + g] = vw[o*128 + 2*c] + vw[o*128 + 2*c + 1];
    }

    // PE-rearranged q weights: [j][t4][o], t4: 0=sin_y,1=cos_y,2=sin_x,3=cos_x
    {
        int j = g >> 8, r = g & 255, t4 = r >> 6, o = r & 63;
        int col = (t4 < 2) ? (2*j + t4) : (64 + 2*j + (t4 - 2));
        d_const[OFF_QWPE + g] = qw[o*128 + col];
    }

    if (g < 32) d_const[OFF_FREQ + g] = __expf(-(float)g * LN1E4_32);
    if (g < 64) d_const[OFF_QB + g]   = qb[g];

    // window-PE biases: kbias[uv][o] = pe_warp[uv] . k_w[o] + k_b[o]
    // warp W handles entry W=(uv,o); lane j handles one frequency.
    const float SW = (float)(2.0 * M_PI / (1.0 + 1e-6));
    int W = g >> 5, j = g & 31;                        // W in [0,256)
    int uv = W >> 6, o = W & 63;
    float uu = (float)(uv >> 1), vv = (float)(uv & 1);
    float f = __expf(-(float)j * LN1E4_32);
    float syv, cyv, sxv, cxv;
    __sincosf(uu * SW * f, &syv, &cyv);
    __sincosf(vv * SW * f, &sxv, &cxv);
    float aK = syv*kw[o*128+2*j] + cyv*kw[o*128+2*j+1]
             + sxv*kw[o*128+64+2*j] + cxv*kw[o*128+64+2*j+1];
    float aV = syv*vw[o*128+2*j] + cyv*vw[o*128+2*j+1]
             + sxv*vw[o*128+64+2*j] + cxv*vw[o*128+64+2*j+1];
    #pragma unroll
    for (int s = 16; s > 0; s >>= 1) {
        aK += __shfl_xor_sync(0xffffffffu, aK, s);
        aV += __shfl_xor_sync(0xffffffffu, aV, s);
    }
    if (j == 0) {
        d_const[OFF_KB + W] = aK + kb[o];
        d_const[OFF_VB + W] = aV + vb[o];
    }
}

// ---------------------------------------------------------------------------
// Q kernel: q = folded-curr matvec + PE matvec + bias, all in packed f32x2.
// ---------------------------------------------------------------------------
__global__ void __launch_bounds__(256, 2) iw_q_kernel(
    const float* __restrict__ curr, const float* __restrict__ flow)
{
    extern __shared__ float sm[];
    for (int i = threadIdx.x; i < 4096; i += 256) sm[QS_QWS  + i] = d_const[OFF_QWS  + i];
    for (int i = threadIdx.x; i < 8192; i += 256) sm[QS_QWPE + i] = d_const[OFF_QWPE + i];
    if (threadIdx.x < 64) sm[QS_QB   + threadIdx.x] = d_const[OFF_QB   + threadIdx.x];
    if (threadIdx.x < 32) sm[QS_FREQ + threadIdx.x] = d_const[OFF_FREQ + threadIdx.x];
    __syncthreads();

    const float* s_qws  = sm + QS_QWS;
    const float* s_qwpe = sm + QS_QWPE;
    const float* s_fr   = sm + QS_FREQ;

    int pix = blockIdx.x * 256 + threadIdx.x;
    int b   = pix >> 16;
    int rem = pix & 65535;
    int yy  = rem >> 8;
    int xx  = rem & 255;

    float2 fl = reinterpret_cast<const float2*>(flow)[pix];
    float gy = (float)yy + fl.y;
    float gx = (float)xx + fl.x;
    float dy = gy - floorf(gy);
    float dx = gx - floorf(gx);

    const float* currB = curr + b*(CH*HWX) + yy*WW + xx;

    u64t q2[32];
    const u64t* qb2 = reinterpret_cast<const u64t*>(sm + QS_QB);
    #pragma unroll
    for (int i = 0; i < 32; i++) q2[i] = qb2[i];

    #pragma unroll 4
    for (int c = 0; c < 64; c++) {
        float fc = __ldg(currB + c*HWX);
        u64t fc2 = pk2(fc, fc);
        const u64t* wc2 = reinterpret_cast<const u64t*>(s_qws + c*64);
        #pragma unroll
        for (int i = 0; i < 32; i++) q2[i] = ffma2(fc2, wc2[i], q2[i]);
    }

    const float PE2 = (float)(2.0 * M_PI / (2.0 + 1e-6));  // card = (U,V) = (2,2)
    float ay = dy * PE2, ax = dx * PE2;
    for (int j = 0; j < 32; j++) {
        float f = s_fr[j];
        float syv, cyv, sxv, cxv;
        __sincosf(ay * f, &syv, &cyv);
        __sincosf(ax * f, &sxv, &cxv);
        u64t sy2 = pk2(syv, syv), cy2 = pk2(cyv, cyv);
        u64t sx2 = pk2(sxv, sxv), cx2 = pk2(cxv, cxv);
        const u64t* wj2 = reinterpret_cast<const u64t*>(s_qwpe + j*256);
        #pragma unroll
        for (int i = 0; i < 32; i++) {
            u64t acc = q2[i];
            acc = ffma2(sy2, wj2[i],      acc);
            acc = ffma2(cy2, wj2[32 + i], acc);
            acc = ffma2(sx2, wj2[64 + i], acc);
            acc = ffma2(cx2, wj2[96 + i], acc);
            q2[i] = acc;
        }
    }

    #pragma unroll
    for (int i = 0; i < 32; i++) {
        float lo, hi; upk2(lo, hi, q2[i]);
        q_scr[(2*i)*NPIX + pix]     = lo;
        q_scr[(2*i + 1)*NPIX + pix] = hi;
    }
}

// ---------------------------------------------------------------------------
// AV kernel: gather + attn + softmax + value pass, packed f32x2 accumulation.
// ---------------------------------------------------------------------------
__global__ void __launch_bounds__(128, 3) iw_av_kernel(
    const float* __restrict__ supp, const float* __restrict__ flow,
    float* __restrict__ out)
{
    extern __shared__ float sm[];
    for (int i = threadIdx.x; i < 4096; i += 128) {
        sm[AS_KWS + i] = d_const[OFF_KWS + i];
        sm[AS_VWS + i] = d_const[OFF_VWS + i];
    }
    for (int i = threadIdx.x; i < 256; i += 128) {
        sm[AS_KB + i] = d_const[OFF_KB + i];
        sm[AS_VB + i] = d_const[OFF_VB + i];
    }
    __syncthreads();

    const float* s_kws = sm + AS_KWS;
    const float* s_vws = sm + AS_VWS;
    const float* s_kb  = sm + AS_KB;
    const float* s_vb  = sm + AS_VB;

    int pix = blockIdx.x * 128 + threadIdx.x;
    int b   = pix >> 16;
    int rem = pix & 65535;
    int yy  = rem >> 8;
    int xx  = rem & 255;

    float2 fl = reinterpret_cast<const float2*>(flow)[pix];
    float gy = (float)yy + fl.y;
    float gx = (float)xx + fl.x;
    int iy = (int)floorf(gy), ix = (int)floorf(gx);
    int r0 = min(max(iy,     0), HH-1);
    int r1 = min(max(iy + 1, 0), HH-1);
    int c0 = min(max(ix,     0), WW-1);
    int c1 = min(max(ix + 1, 0), WW-1);
    int o00 = r0*WW + c0, o01 = r0*WW + c1;
    int o10 = r1*WW + c0, o11 = r1*WW + c1;

    const float* suppB = supp + b*(CH*HWX);

    // load q packed (pairs over o)
    u64t q2[32];
    #pragma unroll
    for (int i = 0; i < 32; i++)
        q2[i] = pk2(q_scr[(2*i)*NPIX + pix], q_scr[(2*i + 1)*NPIX + pix]);

    // -------- attn init: packed bias-dot q . kb[u] --------
    u64t A01[8], A23[8];
    #pragma unroll
    for (int h = 0; h < 8; h++) {
        float av[4];
        #pragma unroll
        for (int u = 0; u < 4; u++) {
            const u64t* kb2 = reinterpret_cast<const u64t*>(s_kb + u*64);
            u64t d2 = fmul2(q2[h*4], kb2[h*4]);
            d2 = ffma2(q2[h*4+1], kb2[h*4+1], d2);
            d2 = ffma2(q2[h*4+2], kb2[h*4+2], d2);
            d2 = ffma2(q2[h*4+3], kb2[h*4+3], d2);
            float lo, hi; upk2(lo, hi, d2);
            av[u] = lo + hi;
        }
        A01[h] = pk2(av[0], av[1]);
        A23[h] = pk2(av[2], av[3]);
    }

    // -------- attn logits: folded qk dot over gathered support --------
    for (int ch = 0; ch < 8; ch++) {
        float f00[8], f01[8], f10[8], f11[8];
        #pragma unroll
        for (int cc = 0; cc < 8; cc++) {
            const float* p = suppB + (ch*8 + cc)*HWX;
            f00[cc] = __ldg(p + o00);
            f01[cc] = __ldg(p + o01);
            f10[cc] = __ldg(p + o10);
            f11[cc] = __ldg(p + o11);
        }
        #pragma unroll
        for (int cc = 0; cc < 8; cc++) {
            const u64t* wc2 = reinterpret_cast<const u64t*>(s_kws + (ch*8 + cc)*64);
            u64t F01 = pk2(f00[cc], f01[cc]);
            u64t F23 = pk2(f10[cc], f11[cc]);
            #pragma unroll
            for (int h = 0; h < 8; h++) {
                u64t d2 = fmul2(q2[h*4], wc2[h*4]);
                d2 = ffma2(q2[h*4+1], wc2[h*4+1], d2);
                d2 = ffma2(q2[h*4+2], wc2[h*4+2], d2);
                d2 = ffma2(q2[h*4+3], wc2[h*4+3], d2);
                float lo, hi; upk2(lo, hi, d2);
                float qk = lo + hi;
                u64t qk2 = pk2(qk, qk);
                A01[h] = ffma2(qk2, F01, A01[h]);
                A23[h] = ffma2(qk2, F23, A23[h]);
            }
        }
    }

    // -------- softmax over the 4 window positions (scale = 8^-0.5) --------
    const float SC = 0.35355339059327376f;
    float attn[8][4];
    #pragma unroll
    for (int h = 0; h < 8; h++) {
        float a0, a1, a2, a3;
        upk2(a0, a1, A01[h]);
        upk2(a2, a3, A23[h]);
        float m = fmaxf(fmaxf(a0, a1), fmaxf(a2, a3));
        float p0 = __expf((a0 - m) * SC);
        float p1 = __expf((a1 - m) * SC);
        float p2 = __expf((a2 - m) * SC);
        float p3 = __expf((a3 - m) * SC);
        float inv = __fdividef(1.0f, p0 + p1 + p2 + p3);
        attn[h][0] = p0*inv; attn[h][1] = p1*inv;
        attn[h][2] = p2*inv; attn[h][3] = p3*inv;
        A01[h] = pk2(attn[h][0], attn[h][1]);
        A23[h] = pk2(attn[h][2], attn[h][3]);
    }

    // -------- output: g-fold over second gather pass, packed out --------
    u64t out2[32];
    #pragma unroll
    for (int i = 0; i < 32; i++) out2[i] = 0ULL;

    for (int ch = 0; ch < 8; ch++) {
        float f00[8], f01[8], f10[8], f11[8];
        #pragma unroll
        for (int cc = 0; cc < 8; cc++) {
            const float* p = suppB + (ch*8 + cc)*HWX;
            f00[cc] = __ldg(p + o00);
            f01[cc] = __ldg(p + o01);
            f10[cc] = __ldg(p + o10);
            f11[cc] = __ldg(p + o11);
        }
        #pragma unroll
        for (int cc = 0; cc < 8; cc++) {
            const u64t* wc2 = reinterpret_cast<const u64t*>(s_vws + (ch*8 + cc)*64);
            u64t F01 = pk2(f00[cc], f01[cc]);
            u64t F23 = pk2(f10[cc], f11[cc]);
            u64t gv2[8];
            #pragma unroll
            for (int h = 0; h < 8; h++) {
                u64t g2 = fmul2(A01[h], F01);
                g2 = ffma2(A23[h], F23, g2);
                float lo, hi; upk2(lo, hi, g2);
                float gv = lo + hi;
                gv2[h] = pk2(gv, gv);
            }
            #pragma unroll
            for (int i = 0; i < 32; i++)
                out2[i] = ffma2(gv2[i >> 2], wc2[i], out2[i]);
        }
    }

    // v pe-bias term + store (scalar; 256 FMA, small)
    float* outB = out + b*(CH*HWX) + yy*WW + xx;
    #pragma unroll
    for (int i = 0; i < 32; i++) {
        float lo, hi; upk2(lo, hi, out2[i]);
        int o0 = 2*i, o1 = 2*i + 1;
        int h = o0 >> 3;
        #pragma unroll
        for (int u = 0; u < 4; u++) {
            lo = fmaf(attn[h][u], s_vb[u*64 + o0], lo);
            hi = fmaf(attn[h][u], s_vb[u*64 + o1], hi);
        }
        outB[o0*HWX] = lo;
        outB[o1*HWX] = hi;
    }
}

// ---------------------------------------------------------------------------
extern "C" void kernel_launch(void* const* d_in, const int* in_sizes, int n_in,
                              void* d_out, int out_size)
{
    const float* supp = (const float*)d_in[0];
    const float* flow = (const float*)d_in[1];
    const float* curr = (const float*)d_in[2];
    const float* qw   = (const float*)d_in[3];
    const float* qb   = (const float*)d_in[4];
    const float* kw   = (const float*)d_in[5];
    const float* kb   = (const float*)d_in[6];
    const float* vw   = (const float*)d_in[7];
    const float* vb   = (const float*)d_in[8];
    float* outp = (float*)d_out;

    cudaFuncSetAttribute(iw_q_kernel,
                         cudaFuncAttributeMaxDynamicSharedMemorySize, QS_N * 4);
    cudaFuncSetAttribute(iw_av_kernel,
                         cudaFuncAttributeMaxDynamicSharedMemorySize, AS_N * 4);

    iw_setup_kernel<<<32, 256>>>(qw, qb, kw, kb, vw, vb);
    iw_q_kernel<<<NPIX / 256, 256, QS_N * 4>>>(curr, flow);
    iw_av_kernel<<<NPIX / 128, 128, AS_N * 4>>>(supp, flow, outp);
}